// round 2
// baseline (speedup 1.0000x reference)
#include <cuda_runtime.h>
#include <math.h>

#define N_MAX 100000
#define E_MAX 1600000

// ---------------- device scratch (static, no allocation) ----------------
__device__ int   g_deg[N_MAX];
__device__ int   g_cursor[N_MAX];
__device__ int   g_excl[N_MAX];
__device__ int   g_bsums[256];
__device__ int   g_boffs[256];
__device__ int   g_rowstart[N_MAX + 1];
__device__ int   g_ebuf[E_MAX];
__device__ float g_y1[N_MAX * 64];   // x @ W_l1   (message source, layer 1)
__device__ float g_r1[N_MAX * 64];   // x @ W_r1 + b_l1
__device__ float g_hid[N_MAX * 64];  // relu(mean + root)
__device__ float g_y2[N_MAX * 40];   // hid @ W_l2
__device__ float g_r2[N_MAX * 40];   // hid @ W_r2 + b_l2

// ---------------- CSR build ----------------
__global__ void zero_kernel(int n) {
    int i = blockIdx.x * blockDim.x + threadIdx.x;
    if (i < n) { g_deg[i] = 0; g_cursor[i] = 0; }
}

__global__ void count_deg_kernel(const int* __restrict__ dst, int e) {
    int i = blockIdx.x * blockDim.x + threadIdx.x;
    if (i < e) atomicAdd(&g_deg[dst[i]], 1);
}

__global__ void scan1_kernel(int n) {
    __shared__ int wsum[32];
    int t = threadIdx.x;
    int i = blockIdx.x * 1024 + t;
    int v = (i < n) ? g_deg[i] : 0;
    int x = v;
#pragma unroll
    for (int o = 1; o < 32; o <<= 1) {
        int u = __shfl_up_sync(0xffffffffu, x, o);
        if ((t & 31) >= o) x += u;
    }
    if ((t & 31) == 31) wsum[t >> 5] = x;
    __syncthreads();
    if (t < 32) {
        int w = wsum[t];
#pragma unroll
        for (int o = 1; o < 32; o <<= 1) {
            int u = __shfl_up_sync(0xffffffffu, w, o);
            if (t >= o) w += u;
        }
        wsum[t] = w;
    }
    __syncthreads();
    int base = (t >= 32) ? wsum[(t >> 5) - 1] : 0;
    int incl = base + x;
    if (i < n) g_excl[i] = incl - v;
    if (t == 1023) g_bsums[blockIdx.x] = incl;
}

__global__ void scan2_kernel(int nb) {
    __shared__ int s[128];
    int t = threadIdx.x;
    int v = (t < nb) ? g_bsums[t] : 0;
    s[t] = v;
    __syncthreads();
    for (int o = 1; o < 128; o <<= 1) {
        int u = (t >= o) ? s[t - o] : 0;
        __syncthreads();
        s[t] += u;
        __syncthreads();
    }
    g_boffs[t] = s[t] - v;  // exclusive
}

__global__ void scan3_kernel(int n, int e) {
    int i = blockIdx.x * blockDim.x + threadIdx.x;
    if (i < n) g_rowstart[i] = g_excl[i] + g_boffs[i >> 10];
    if (i == n) g_rowstart[n] = e;
}

__global__ void fill_csr_kernel(const int* __restrict__ src,
                                const int* __restrict__ dst, int e) {
    int i = blockIdx.x * blockDim.x + threadIdx.x;
    if (i < e) {
        int d = dst[i];
        int pos = atomicAdd(&g_cursor[d], 1);
        g_ebuf[g_rowstart[d] + pos] = src[i];
    }
}

// ---------------- GEMM layer 1: y1 = x@Wl, r1 = x@Wr + b ----------------
// block = (64,4): 64 out cols x 4 node-groups of 16 nodes -> 64 nodes/block
__global__ __launch_bounds__(256) void gemm1_kernel(
    const float* __restrict__ x, const float* __restrict__ Wl,
    const float* __restrict__ Wr, const float* __restrict__ bl, int n) {
    __shared__ float xs[128 * 68];  // transposed [k][node], padded
    int node0 = blockIdx.x * 64;
    int tid = threadIdx.y * 64 + threadIdx.x;
    for (int i = tid; i < 64 * 128; i += 256) {
        int nl = i >> 7, k = i & 127;
        float v = (node0 + nl < n) ? x[(node0 + nl) * 128 + k] : 0.f;
        xs[k * 68 + nl] = v;
    }
    __syncthreads();
    int c = threadIdx.x;
    int g = threadIdx.y;
    float accl[16], accr[16];
#pragma unroll
    for (int j = 0; j < 16; j++) { accl[j] = 0.f; accr[j] = 0.f; }
    const float* xb = &xs[g * 16];
#pragma unroll 4
    for (int k = 0; k < 128; k++) {
        float wl = Wl[k * 64 + c];
        float wr = Wr[k * 64 + c];
        float4 v0 = *(const float4*)&xb[k * 68];
        float4 v1 = *(const float4*)&xb[k * 68 + 4];
        float4 v2 = *(const float4*)&xb[k * 68 + 8];
        float4 v3 = *(const float4*)&xb[k * 68 + 12];
        float xv[16];
        xv[0] = v0.x; xv[1] = v0.y; xv[2] = v0.z; xv[3] = v0.w;
        xv[4] = v1.x; xv[5] = v1.y; xv[6] = v1.z; xv[7] = v1.w;
        xv[8] = v2.x; xv[9] = v2.y; xv[10] = v2.z; xv[11] = v2.w;
        xv[12] = v3.x; xv[13] = v3.y; xv[14] = v3.z; xv[15] = v3.w;
#pragma unroll
        for (int j = 0; j < 16; j++) {
            accl[j] += wl * xv[j];
            accr[j] += wr * xv[j];
        }
    }
    float bias = bl[c];
#pragma unroll
    for (int j = 0; j < 16; j++) {
        int node = node0 + g * 16 + j;
        if (node < n) {
            g_y1[node * 64 + c] = accl[j];
            g_r1[node * 64 + c] = accr[j] + bias;
        }
    }
}

// ---------------- combine layer 1: hid = relu(gather_mean(y1) + r1) -----
__global__ void combine1_kernel(int n) {
    int node = (blockIdx.x * blockDim.x + threadIdx.x) >> 5;
    int lane = threadIdx.x & 31;
    if (node >= n) return;
    int s = g_rowstart[node], e = g_rowstart[node + 1];
    float inv = 1.f / (float)max(e - s, 1);
    float a0 = 0.f, a1 = 0.f;
    for (int i = s; i < e; i++) {
        int nb = g_ebuf[i];
        float2 v = *(const float2*)&g_y1[nb * 64 + lane * 2];
        a0 += v.x; a1 += v.y;
    }
    float2 r = *(const float2*)&g_r1[node * 64 + lane * 2];
    float h0 = fmaxf(a0 * inv + r.x, 0.f);
    float h1 = fmaxf(a1 * inv + r.y, 0.f);
    *(float2*)&g_hid[node * 64 + lane * 2] = make_float2(h0, h1);
}

// ---------------- GEMM layer 2: y2 = hid@Wl2, r2 = hid@Wr2 + b2 ---------
__global__ __launch_bounds__(256) void gemm2_kernel(
    const float* __restrict__ Wl, const float* __restrict__ Wr,
    const float* __restrict__ bl, int n) {
    __shared__ float xs[64 * 68];
    int node0 = blockIdx.x * 64;
    int tid = threadIdx.y * 64 + threadIdx.x;
    for (int i = tid; i < 64 * 64; i += 256) {
        int nl = i >> 6, k = i & 63;
        float v = (node0 + nl < n) ? g_hid[(node0 + nl) * 64 + k] : 0.f;
        xs[k * 68 + nl] = v;
    }
    __syncthreads();
    int c = threadIdx.x;
    int g = threadIdx.y;
    int cc = c < 40 ? c : 39;  // clamp for safe loads; stores guarded
    float accl[16], accr[16];
#pragma unroll
    for (int j = 0; j < 16; j++) { accl[j] = 0.f; accr[j] = 0.f; }
    const float* xb = &xs[g * 16];
#pragma unroll 4
    for (int k = 0; k < 64; k++) {
        float wl = Wl[k * 40 + cc];
        float wr = Wr[k * 40 + cc];
        float4 v0 = *(const float4*)&xb[k * 68];
        float4 v1 = *(const float4*)&xb[k * 68 + 4];
        float4 v2 = *(const float4*)&xb[k * 68 + 8];
        float4 v3 = *(const float4*)&xb[k * 68 + 12];
        float xv[16];
        xv[0] = v0.x; xv[1] = v0.y; xv[2] = v0.z; xv[3] = v0.w;
        xv[4] = v1.x; xv[5] = v1.y; xv[6] = v1.z; xv[7] = v1.w;
        xv[8] = v2.x; xv[9] = v2.y; xv[10] = v2.z; xv[11] = v2.w;
        xv[12] = v3.x; xv[13] = v3.y; xv[14] = v3.z; xv[15] = v3.w;
#pragma unroll
        for (int j = 0; j < 16; j++) {
            accl[j] += wl * xv[j];
            accr[j] += wr * xv[j];
        }
    }
    if (c < 40) {
        float bias = bl[c];
#pragma unroll
        for (int j = 0; j < 16; j++) {
            int node = node0 + g * 16 + j;
            if (node < n) {
                g_y2[node * 40 + c] = accl[j];
                g_r2[node * 40 + c] = accr[j] + bias;
            }
        }
    }
}

// ------- combine layer 2: out = log_softmax(gather_mean(y2) + r2) -------
__global__ void combine2_kernel(float* __restrict__ out, int n) {
    int node = (blockIdx.x * blockDim.x + threadIdx.x) >> 5;
    int lane = threadIdx.x & 31;
    if (node >= n) return;
    int s = g_rowstart[node], e = g_rowstart[node + 1];
    float inv = 1.f / (float)max(e - s, 1);
    float a0 = 0.f, a1 = 0.f;
    for (int i = s; i < e; i++) {
        int nb = g_ebuf[i];
        a0 += g_y2[nb * 40 + lane];
        if (lane < 8) a1 += g_y2[nb * 40 + 32 + lane];
    }
    const float NEG_INF = __int_as_float(0xff800000);
    float v0 = a0 * inv + g_r2[node * 40 + lane];
    float v1 = (lane < 8) ? (a1 * inv + g_r2[node * 40 + 32 + lane]) : NEG_INF;
    float m = fmaxf(v0, v1);
#pragma unroll
    for (int o = 16; o > 0; o >>= 1) m = fmaxf(m, __shfl_xor_sync(0xffffffffu, m, o));
    float sum = expf(v0 - m) + ((lane < 8) ? expf(v1 - m) : 0.f);
#pragma unroll
    for (int o = 16; o > 0; o >>= 1) sum += __shfl_xor_sync(0xffffffffu, sum, o);
    float lse = logf(sum);
    out[node * 40 + lane] = v0 - m - lse;
    if (lane < 8) out[node * 40 + 32 + lane] = v1 - m - lse;
}

// ---------------- launch ----------------
extern "C" void kernel_launch(void* const* d_in, const int* in_sizes, int n_in,
                              void* d_out, int out_size) {
    const float* x   = (const float*)d_in[0];
    const int*   ei  = (const int*)d_in[1];   // int64 inputs are delivered as int32
    const float* Wl1 = (const float*)d_in[2];
    const float* bl1 = (const float*)d_in[3];
    const float* Wr1 = (const float*)d_in[4];
    const float* Wl2 = (const float*)d_in[5];
    const float* bl2 = (const float*)d_in[6];
    const float* Wr2 = (const float*)d_in[7];
    float* out = (float*)d_out;

    int n = in_sizes[0] / 128;
    int e = in_sizes[1] / 2;
    const int* src = ei;       // edge_index[0]
    const int* dst = ei + e;   // edge_index[1]

    zero_kernel<<<(n + 255) / 256, 256>>>(n);
    count_deg_kernel<<<(e + 255) / 256, 256>>>(dst, e);
    int nb = (n + 1023) / 1024;
    scan1_kernel<<<nb, 1024>>>(n);
    scan2_kernel<<<1, 128>>>(nb);
    scan3_kernel<<<(n + 1 + 255) / 256, 256>>>(n, e);
    fill_csr_kernel<<<(e + 255) / 256, 256>>>(src, dst, e);

    dim3 gblk(64, 4);
    gemm1_kernel<<<(n + 63) / 64, gblk>>>(x, Wl1, Wr1, bl1, n);
    combine1_kernel<<<(n * 32 + 255) / 256, 256>>>(n);
    gemm2_kernel<<<(n + 63) / 64, gblk>>>(Wl2, Wr2, bl2, n);
    combine2_kernel<<<(n * 32 + 255) / 256, 256>>>(out, n);
}

// round 3
// speedup vs baseline: 1.0632x; 1.0632x over previous
#include <cuda_runtime.h>
#include <cuda_fp16.h>
#include <math.h>

#define N_MAX 100000
#define E_MAX 1600000

// ---------------- device scratch (static, no allocation) ----------------
__device__ int    g_deg[N_MAX];
__device__ int    g_cursor[N_MAX];
__device__ int    g_excl[N_MAX];
__device__ int    g_bsums[256];
__device__ int    g_boffs[256];
__device__ int    g_rowstart[N_MAX + 1];
__device__ int    g_ebuf[E_MAX];
__device__ __half g_y1h[N_MAX * 64];   // fp16(x @ W_l1)
__device__ float  g_r1[N_MAX * 64];    // x @ W_r1 + b_l1
__device__ float  g_hid[N_MAX * 64];   // relu(mean + root)
__device__ __half g_y2h[N_MAX * 40];   // fp16(hid @ W_l2)
__device__ float  g_r2[N_MAX * 40];    // hid @ W_r2 + b_l2

// ---------------- CSR build ----------------
__global__ void zero_kernel(int n) {
    int i = blockIdx.x * blockDim.x + threadIdx.x;
    if (i < n) { g_deg[i] = 0; g_cursor[i] = 0; }
}

__global__ void count_deg_kernel(const int* __restrict__ dst, int e) {
    int i = blockIdx.x * blockDim.x + threadIdx.x;
    if (i < e) atomicAdd(&g_deg[dst[i]], 1);
}

__global__ void scan1_kernel(int n) {
    __shared__ int wsum[32];
    int t = threadIdx.x;
    int i = blockIdx.x * 1024 + t;
    int v = (i < n) ? g_deg[i] : 0;
    int x = v;
#pragma unroll
    for (int o = 1; o < 32; o <<= 1) {
        int u = __shfl_up_sync(0xffffffffu, x, o);
        if ((t & 31) >= o) x += u;
    }
    if ((t & 31) == 31) wsum[t >> 5] = x;
    __syncthreads();
    if (t < 32) {
        int w = wsum[t];
#pragma unroll
        for (int o = 1; o < 32; o <<= 1) {
            int u = __shfl_up_sync(0xffffffffu, w, o);
            if (t >= o) w += u;
        }
        wsum[t] = w;
    }
    __syncthreads();
    int base = (t >= 32) ? wsum[(t >> 5) - 1] : 0;
    int incl = base + x;
    if (i < n) g_excl[i] = incl - v;
    if (t == 1023) g_bsums[blockIdx.x] = incl;
}

__global__ void scan2_kernel(int nb) {
    __shared__ int s[128];
    int t = threadIdx.x;
    int v = (t < nb) ? g_bsums[t] : 0;
    s[t] = v;
    __syncthreads();
    for (int o = 1; o < 128; o <<= 1) {
        int u = (t >= o) ? s[t - o] : 0;
        __syncthreads();
        s[t] += u;
        __syncthreads();
    }
    g_boffs[t] = s[t] - v;  // exclusive
}

__global__ void scan3_kernel(int n, int e) {
    int i = blockIdx.x * blockDim.x + threadIdx.x;
    if (i < n) g_rowstart[i] = g_excl[i] + g_boffs[i >> 10];
    if (i == n) g_rowstart[n] = e;
}

__global__ void fill_csr_kernel(const int* __restrict__ src,
                                const int* __restrict__ dst, int e) {
    int i = blockIdx.x * blockDim.x + threadIdx.x;
    if (i < e) {
        int d = dst[i];
        int pos = atomicAdd(&g_cursor[d], 1);
        g_ebuf[g_rowstart[d] + pos] = src[i];
    }
}

// ---------------- GEMM layer 1: y1 = fp16(x@Wl), r1 = x@Wr + b ----------
__global__ __launch_bounds__(256) void gemm1_kernel(
    const float* __restrict__ x, const float* __restrict__ Wl,
    const float* __restrict__ Wr, const float* __restrict__ bl, int n) {
    __shared__ float xs[128 * 68];  // transposed [k][node], padded
    int node0 = blockIdx.x * 64;
    int tid = threadIdx.y * 64 + threadIdx.x;
    for (int i = tid; i < 64 * 128; i += 256) {
        int nl = i >> 7, k = i & 127;
        float v = (node0 + nl < n) ? x[(node0 + nl) * 128 + k] : 0.f;
        xs[k * 68 + nl] = v;
    }
    __syncthreads();
    int c = threadIdx.x;
    int g = threadIdx.y;
    float accl[16], accr[16];
#pragma unroll
    for (int j = 0; j < 16; j++) { accl[j] = 0.f; accr[j] = 0.f; }
    const float* xb = &xs[g * 16];
#pragma unroll 4
    for (int k = 0; k < 128; k++) {
        float wl = Wl[k * 64 + c];
        float wr = Wr[k * 64 + c];
        float4 v0 = *(const float4*)&xb[k * 68];
        float4 v1 = *(const float4*)&xb[k * 68 + 4];
        float4 v2 = *(const float4*)&xb[k * 68 + 8];
        float4 v3 = *(const float4*)&xb[k * 68 + 12];
        float xv[16];
        xv[0] = v0.x; xv[1] = v0.y; xv[2] = v0.z; xv[3] = v0.w;
        xv[4] = v1.x; xv[5] = v1.y; xv[6] = v1.z; xv[7] = v1.w;
        xv[8] = v2.x; xv[9] = v2.y; xv[10] = v2.z; xv[11] = v2.w;
        xv[12] = v3.x; xv[13] = v3.y; xv[14] = v3.z; xv[15] = v3.w;
#pragma unroll
        for (int j = 0; j < 16; j++) {
            accl[j] += wl * xv[j];
            accr[j] += wr * xv[j];
        }
    }
    float bias = bl[c];
#pragma unroll
    for (int j = 0; j < 16; j++) {
        int node = node0 + g * 16 + j;
        if (node < n) {
            g_y1h[node * 64 + c] = __float2half_rn(accl[j]);
            g_r1[node * 64 + c] = accr[j] + bias;
        }
    }
}

// ------- combine layer 1: hid = relu(gather_mean(y1) + r1) --------------
// one warp per node; lane covers 2 channels via half2; 4-deep MLP
__global__ void combine1_kernel(int n) {
    int node = (blockIdx.x * blockDim.x + threadIdx.x) >> 5;
    int lane = threadIdx.x & 31;
    if (node >= n) return;
    int s = g_rowstart[node], e = g_rowstart[node + 1];
    float inv = 1.f / (float)max(e - s, 1);
    const __half2* y1 = (const __half2*)g_y1h;
    float a0 = 0.f, a1 = 0.f, b0 = 0.f, b1 = 0.f;
    float c0 = 0.f, c1 = 0.f, d0 = 0.f, d1 = 0.f;
    for (int base = s; base < e; base += 32) {
        int cnt = min(32, e - base);
        int idx = (lane < cnt) ? g_ebuf[base + lane] : 0;
        int j = 0;
        for (; j + 4 <= cnt; j += 4) {
            int n0 = __shfl_sync(0xffffffffu, idx, j);
            int n1 = __shfl_sync(0xffffffffu, idx, j + 1);
            int n2 = __shfl_sync(0xffffffffu, idx, j + 2);
            int n3 = __shfl_sync(0xffffffffu, idx, j + 3);
            float2 v0 = __half22float2(y1[n0 * 32 + lane]);
            float2 v1 = __half22float2(y1[n1 * 32 + lane]);
            float2 v2 = __half22float2(y1[n2 * 32 + lane]);
            float2 v3 = __half22float2(y1[n3 * 32 + lane]);
            a0 += v0.x; a1 += v0.y;
            b0 += v1.x; b1 += v1.y;
            c0 += v2.x; c1 += v2.y;
            d0 += v3.x; d1 += v3.y;
        }
        for (; j < cnt; j++) {
            int n0 = __shfl_sync(0xffffffffu, idx, j);
            float2 v0 = __half22float2(y1[n0 * 32 + lane]);
            a0 += v0.x; a1 += v0.y;
        }
    }
    a0 += b0 + c0 + d0;
    a1 += b1 + c1 + d1;
    float2 r = *(const float2*)&g_r1[node * 64 + lane * 2];
    float h0 = fmaxf(a0 * inv + r.x, 0.f);
    float h1 = fmaxf(a1 * inv + r.y, 0.f);
    *(float2*)&g_hid[node * 64 + lane * 2] = make_float2(h0, h1);
}

// ---------------- GEMM layer 2: y2 = fp16(hid@Wl2), r2 = hid@Wr2 + b2 ---
__global__ __launch_bounds__(256) void gemm2_kernel(
    const float* __restrict__ Wl, const float* __restrict__ Wr,
    const float* __restrict__ bl, int n) {
    __shared__ float xs[64 * 68];
    int node0 = blockIdx.x * 64;
    int tid = threadIdx.y * 64 + threadIdx.x;
    for (int i = tid; i < 64 * 64; i += 256) {
        int nl = i >> 6, k = i & 63;
        float v = (node0 + nl < n) ? g_hid[(node0 + nl) * 64 + k] : 0.f;
        xs[k * 68 + nl] = v;
    }
    __syncthreads();
    int c = threadIdx.x;
    int g = threadIdx.y;
    int cc = c < 40 ? c : 39;  // clamp for safe loads; stores guarded
    float accl[16], accr[16];
#pragma unroll
    for (int j = 0; j < 16; j++) { accl[j] = 0.f; accr[j] = 0.f; }
    const float* xb = &xs[g * 16];
#pragma unroll 4
    for (int k = 0; k < 64; k++) {
        float wl = Wl[k * 40 + cc];
        float wr = Wr[k * 40 + cc];
        float4 v0 = *(const float4*)&xb[k * 68];
        float4 v1 = *(const float4*)&xb[k * 68 + 4];
        float4 v2 = *(const float4*)&xb[k * 68 + 8];
        float4 v3 = *(const float4*)&xb[k * 68 + 12];
        float xv[16];
        xv[0] = v0.x; xv[1] = v0.y; xv[2] = v0.z; xv[3] = v0.w;
        xv[4] = v1.x; xv[5] = v1.y; xv[6] = v1.z; xv[7] = v1.w;
        xv[8] = v2.x; xv[9] = v2.y; xv[10] = v2.z; xv[11] = v2.w;
        xv[12] = v3.x; xv[13] = v3.y; xv[14] = v3.z; xv[15] = v3.w;
#pragma unroll
        for (int j = 0; j < 16; j++) {
            accl[j] += wl * xv[j];
            accr[j] += wr * xv[j];
        }
    }
    if (c < 40) {
        float bias = bl[c];
#pragma unroll
        for (int j = 0; j < 16; j++) {
            int node = node0 + g * 16 + j;
            if (node < n) {
                g_y2h[node * 40 + c] = __float2half_rn(accl[j]);
                g_r2[node * 40 + c] = accr[j] + bias;
            }
        }
    }
}

// ------- combine layer 2: out = log_softmax(gather_mean(y2) + r2) -------
// one warp per node; lanes 0..19 each cover 2 channels via half2
__global__ void combine2_kernel(float* __restrict__ out, int n) {
    int node = (blockIdx.x * blockDim.x + threadIdx.x) >> 5;
    int lane = threadIdx.x & 31;
    if (node >= n) return;
    int s = g_rowstart[node], e = g_rowstart[node + 1];
    float inv = 1.f / (float)max(e - s, 1);
    const __half2* y2 = (const __half2*)g_y2h;
    bool act = lane < 20;
    float a0 = 0.f, a1 = 0.f, b0 = 0.f, b1 = 0.f;
    float c0 = 0.f, c1 = 0.f, d0 = 0.f, d1 = 0.f;
    for (int base = s; base < e; base += 32) {
        int cnt = min(32, e - base);
        int idx = (lane < cnt) ? g_ebuf[base + lane] : 0;
        int j = 0;
        for (; j + 4 <= cnt; j += 4) {
            int n0 = __shfl_sync(0xffffffffu, idx, j);
            int n1 = __shfl_sync(0xffffffffu, idx, j + 1);
            int n2 = __shfl_sync(0xffffffffu, idx, j + 2);
            int n3 = __shfl_sync(0xffffffffu, idx, j + 3);
            if (act) {
                float2 v0 = __half22float2(y2[n0 * 20 + lane]);
                float2 v1 = __half22float2(y2[n1 * 20 + lane]);
                float2 v2 = __half22float2(y2[n2 * 20 + lane]);
                float2 v3 = __half22float2(y2[n3 * 20 + lane]);
                a0 += v0.x; a1 += v0.y;
                b0 += v1.x; b1 += v1.y;
                c0 += v2.x; c1 += v2.y;
                d0 += v3.x; d1 += v3.y;
            }
        }
        for (; j < cnt; j++) {
            int n0 = __shfl_sync(0xffffffffu, idx, j);
            if (act) {
                float2 v0 = __half22float2(y2[n0 * 20 + lane]);
                a0 += v0.x; a1 += v0.y;
            }
        }
    }
    a0 += b0 + c0 + d0;
    a1 += b1 + c1 + d1;
    const float NEG_INF = __int_as_float(0xff800000);
    float v0 = NEG_INF, v1 = NEG_INF;
    if (act) {
        v0 = a0 * inv + g_r2[node * 40 + 2 * lane];
        v1 = a1 * inv + g_r2[node * 40 + 2 * lane + 1];
    }
    float m = fmaxf(v0, v1);
#pragma unroll
    for (int o = 16; o > 0; o >>= 1) m = fmaxf(m, __shfl_xor_sync(0xffffffffu, m, o));
    float sum = act ? (expf(v0 - m) + expf(v1 - m)) : 0.f;
#pragma unroll
    for (int o = 16; o > 0; o >>= 1) sum += __shfl_xor_sync(0xffffffffu, sum, o);
    float lse = logf(sum);
    if (act) {
        out[node * 40 + 2 * lane] = v0 - m - lse;
        out[node * 40 + 2 * lane + 1] = v1 - m - lse;
    }
}

// ---------------- launch ----------------
extern "C" void kernel_launch(void* const* d_in, const int* in_sizes, int n_in,
                              void* d_out, int out_size) {
    const float* x   = (const float*)d_in[0];
    const int*   ei  = (const int*)d_in[1];   // int64 inputs delivered as int32
    const float* Wl1 = (const float*)d_in[2];
    const float* bl1 = (const float*)d_in[3];
    const float* Wr1 = (const float*)d_in[4];
    const float* Wl2 = (const float*)d_in[5];
    const float* bl2 = (const float*)d_in[6];
    const float* Wr2 = (const float*)d_in[7];
    float* out = (float*)d_out;

    int n = in_sizes[0] / 128;
    int e = in_sizes[1] / 2;
    const int* src = ei;       // edge_index[0]
    const int* dst = ei + e;   // edge_index[1]

    // Fork a side stream for the CSR build so it overlaps gemm1
    // (kernel_launch is only invoked a couple of times — correctness + capture —
    // so creating stream/events per call leaks nothing meaningful and keeps
    // every call doing identical work).
    cudaStream_t s2;
    cudaStreamCreateWithFlags(&s2, cudaStreamNonBlocking);
    cudaEvent_t evFork, evJoin;
    cudaEventCreateWithFlags(&evFork, cudaEventDisableTiming);
    cudaEventCreateWithFlags(&evJoin, cudaEventDisableTiming);

    cudaEventRecord(evFork, 0);
    cudaStreamWaitEvent(s2, evFork, 0);

    // CSR chain on the side stream
    zero_kernel<<<(n + 255) / 256, 256, 0, s2>>>(n);
    count_deg_kernel<<<(e + 255) / 256, 256, 0, s2>>>(dst, e);
    int nb = (n + 1023) / 1024;
    scan1_kernel<<<nb, 1024, 0, s2>>>(n);
    scan2_kernel<<<1, 128, 0, s2>>>(nb);
    scan3_kernel<<<(n + 1 + 255) / 256, 256, 0, s2>>>(n, e);
    fill_csr_kernel<<<(e + 255) / 256, 256, 0, s2>>>(src, dst, e);
    cudaEventRecord(evJoin, s2);

    // gemm1 on the main stream, concurrent with CSR build
    dim3 gblk(64, 4);
    gemm1_kernel<<<(n + 63) / 64, gblk>>>(x, Wl1, Wr1, bl1, n);

    // join, then the dependent tail
    cudaStreamWaitEvent(0, evJoin, 0);
    combine1_kernel<<<(n * 32 + 255) / 256, 256>>>(n);
    gemm2_kernel<<<(n + 63) / 64, gblk>>>(Wl2, Wr2, bl2, n);
    combine2_kernel<<<(n * 32 + 255) / 256, 256>>>(out, n);
}

// round 5
// speedup vs baseline: 1.4635x; 1.3765x over previous
#include <cuda_runtime.h>
#include <cuda_fp16.h>
#include <mma.h>
#include <math.h>
#include <stdint.h>

using namespace nvcuda;

#define N_MAX 100000
#define E_MAX 1600000

// ---------------- device scratch (static, no allocation) ----------------
__device__ int    g_deg[N_MAX];
__device__ int    g_cursor[N_MAX];
__device__ int    g_excl[N_MAX];
__device__ int    g_bsums[256];
__device__ int    g_boffs[256];
__device__ int    g_rowstart[N_MAX + 1];
__device__ int    g_ebuf[E_MAX];
__device__ __align__(16) __half g_y1h[N_MAX * 64]; // fp16(x @ W_l1)
__device__ __align__(16) float  g_r1[N_MAX * 64];  // x @ W_r1 + b_l1
__device__ __align__(16) __half g_hid[N_MAX * 64]; // fp16(relu(mean + root))
__device__ __align__(16) __half g_y2h[N_MAX * 40]; // fp16(hid @ W_l2)
__device__ __align__(16) float  g_r2[N_MAX * 40];  // hid @ W_r2 + b_l2

// ---------------- CSR build ----------------
__global__ void zero_kernel(int n) {
    int i = blockIdx.x * blockDim.x + threadIdx.x;
    if (i < n) { g_deg[i] = 0; g_cursor[i] = 0; }
}

__global__ void count_deg_kernel(const int* __restrict__ dst, int e) {
    int i = blockIdx.x * blockDim.x + threadIdx.x;
    if (i < e) atomicAdd(&g_deg[dst[i]], 1);
}

__global__ void scan1_kernel(int n) {
    __shared__ int wsum[32];
    int t = threadIdx.x;
    int i = blockIdx.x * 1024 + t;
    int v = (i < n) ? g_deg[i] : 0;
    int x = v;
#pragma unroll
    for (int o = 1; o < 32; o <<= 1) {
        int u = __shfl_up_sync(0xffffffffu, x, o);
        if ((t & 31) >= o) x += u;
    }
    if ((t & 31) == 31) wsum[t >> 5] = x;
    __syncthreads();
    if (t < 32) {
        int w = wsum[t];
#pragma unroll
        for (int o = 1; o < 32; o <<= 1) {
            int u = __shfl_up_sync(0xffffffffu, w, o);
            if (t >= o) w += u;
        }
        wsum[t] = w;
    }
    __syncthreads();
    int base = (t >= 32) ? wsum[(t >> 5) - 1] : 0;
    int incl = base + x;
    if (i < n) g_excl[i] = incl - v;
    if (t == 1023) g_bsums[blockIdx.x] = incl;
}

__global__ void scan2_kernel(int nb) {
    __shared__ int s[128];
    int t = threadIdx.x;
    int v = (t < nb) ? g_bsums[t] : 0;
    s[t] = v;
    __syncthreads();
    for (int o = 1; o < 128; o <<= 1) {
        int u = (t >= o) ? s[t - o] : 0;
        __syncthreads();
        s[t] += u;
        __syncthreads();
    }
    g_boffs[t] = s[t] - v;  // exclusive
}

__global__ void scan3_kernel(int n, int e) {
    int i = blockIdx.x * blockDim.x + threadIdx.x;
    if (i < n) g_rowstart[i] = g_excl[i] + g_boffs[i >> 10];
    if (i == n) g_rowstart[n] = e;
}

__global__ void fill_csr_kernel(const int* __restrict__ src,
                                const int* __restrict__ dst, int e) {
    int i = blockIdx.x * blockDim.x + threadIdx.x;
    if (i < e) {
        int d = dst[i];
        int pos = atomicAdd(&g_cursor[d], 1);
        g_ebuf[g_rowstart[d] + pos] = src[i];
    }
}

// ---------------- layer-1 HMMA GEMM: C[128,128] = x_tile @ [Wl1|Wr1] ----
// smem A: half[128][136], B: half[128][136]; C reuses the same buffer (float[128][136])
#define LDA1 136
__global__ __launch_bounds__(256) void gemm1_kernel(
    const float* __restrict__ x, const float* __restrict__ Wl,
    const float* __restrict__ Wr, const float* __restrict__ bl, int n) {
    extern __shared__ char smem[];
    __half* As = (__half*)smem;
    __half* Bs = (__half*)(smem + 128 * LDA1 * 2);
    float*  Cs = (float*)smem;
    int tid = threadIdx.x;
    int node0 = blockIdx.x * 128;

    // A: 128 nodes x 128 feats fp32 -> fp16
    for (int i = tid; i < 128 * 32; i += 256) {
        int row = i >> 5, c4 = i & 31;
        int gr = node0 + row;
        float4 v = (gr < n) ? ((const float4*)x)[gr * 32 + c4]
                            : make_float4(0.f, 0.f, 0.f, 0.f);
        __half2 h0 = __floats2half2_rn(v.x, v.y);
        __half2 h1 = __floats2half2_rn(v.z, v.w);
        *(__half2*)&As[row * LDA1 + c4 * 4] = h0;
        *(__half2*)&As[row * LDA1 + c4 * 4 + 2] = h1;
    }
    // B: [k][0..63] = Wl1, [k][64..127] = Wr1  (K-major row-major, as stored)
    for (int i = tid; i < 128 * 64; i += 256) {
        int k = i >> 6, c = i & 63;
        Bs[k * LDA1 + c] = __float2half_rn(Wl[k * 64 + c]);
        Bs[k * LDA1 + 64 + c] = __float2half_rn(Wr[k * 64 + c]);
    }
    __syncthreads();

    int wid = tid >> 5;
    int wr = (wid >> 1) * 32;   // warp row tile
    int wc = (wid & 1) * 64;    // warp col tile
    wmma::fragment<wmma::accumulator, 16, 16, 16, float> acc[2][4];
#pragma unroll
    for (int i = 0; i < 2; i++)
#pragma unroll
        for (int j = 0; j < 4; j++) wmma::fill_fragment(acc[i][j], 0.f);

#pragma unroll
    for (int k = 0; k < 128; k += 16) {
        wmma::fragment<wmma::matrix_a, 16, 16, 16, __half, wmma::row_major> af[2];
        wmma::fragment<wmma::matrix_b, 16, 16, 16, __half, wmma::row_major> bf[4];
        wmma::load_matrix_sync(af[0], &As[wr * LDA1 + k], LDA1);
        wmma::load_matrix_sync(af[1], &As[(wr + 16) * LDA1 + k], LDA1);
#pragma unroll
        for (int j = 0; j < 4; j++)
            wmma::load_matrix_sync(bf[j], &Bs[k * LDA1 + wc + j * 16], LDA1);
#pragma unroll
        for (int i = 0; i < 2; i++)
#pragma unroll
            for (int j = 0; j < 4; j++)
                wmma::mma_sync(acc[i][j], af[i], bf[j], acc[i][j]);
    }
    __syncthreads();  // done reading A/B; reuse as C
#pragma unroll
    for (int i = 0; i < 2; i++)
#pragma unroll
        for (int j = 0; j < 4; j++)
            wmma::store_matrix_sync(&Cs[(wr + i * 16) * LDA1 + wc + j * 16],
                                    acc[i][j], LDA1, wmma::mem_row_major);
    __syncthreads();

    // epilogue: 2 threads per row; half 0 -> y1h fp16, half 1 -> r1 + bias
    int row = tid >> 1, half = tid & 1;
    int m = node0 + row;
    if (m < n) {
        if (half == 0) {
            uint32_t* dst = (uint32_t*)&g_y1h[m * 64];
            const float* c = &Cs[row * LDA1];
#pragma unroll
            for (int j = 0; j < 64; j += 2) {
                __half2 h = __floats2half2_rn(c[j], c[j + 1]);
                dst[j >> 1] = *reinterpret_cast<uint32_t*>(&h);
            }
        } else {
            float4* dst = (float4*)&g_r1[m * 64];
            const float* c = &Cs[row * LDA1 + 64];
#pragma unroll
            for (int j = 0; j < 64; j += 4)
                dst[j >> 2] = make_float4(c[j] + bl[j], c[j + 1] + bl[j + 1],
                                          c[j + 2] + bl[j + 2], c[j + 3] + bl[j + 3]);
        }
    }
}

// ---------------- layer-2 HMMA GEMM: C[128,80] = hid_tile @ [Wl2|Wr2] ---
#define LDA2 72
#define LDB2 88
__global__ __launch_bounds__(256) void gemm2_kernel(
    const float* __restrict__ Wl, const float* __restrict__ Wr,
    const float* __restrict__ bl, int n) {
    extern __shared__ char smem[];
    __half* As = (__half*)smem;                       // [128][72]
    __half* Bs = (__half*)(smem + 128 * LDA2 * 2);    // [64][88]
    float*  Cs = (float*)smem;                        // reuse: [128][88]
    int tid = threadIdx.x;
    int node0 = blockIdx.x * 128;

    // A: g_hid fp16 direct (128 rows x 64 cols = 8 uint4 per row)
    for (int i = tid; i < 128 * 8; i += 256) {
        int row = i >> 3, c8 = i & 7;
        int gr = node0 + row;
        uint4 v = (gr < n) ? ((const uint4*)g_hid)[gr * 8 + c8] : make_uint4(0, 0, 0, 0);
        *(uint4*)&As[row * LDA2 + c8 * 8] = v;
    }
    // B: [k][0..39] = Wl2, [k][40..79] = Wr2
    for (int i = tid; i < 64 * 40; i += 256) {
        int k = i / 40, c = i % 40;
        Bs[k * LDB2 + c] = __float2half_rn(Wl[k * 40 + c]);
        Bs[k * LDB2 + 40 + c] = __float2half_rn(Wr[k * 40 + c]);
    }
    __syncthreads();

    int wid = tid >> 5;
    int wr = wid * 16;  // each warp: one 16-row strip x 80 cols
    wmma::fragment<wmma::accumulator, 16, 16, 16, float> acc[5];
#pragma unroll
    for (int j = 0; j < 5; j++) wmma::fill_fragment(acc[j], 0.f);
#pragma unroll
    for (int k = 0; k < 64; k += 16) {
        wmma::fragment<wmma::matrix_a, 16, 16, 16, __half, wmma::row_major> af;
        wmma::fragment<wmma::matrix_b, 16, 16, 16, __half, wmma::row_major> bf[5];
        wmma::load_matrix_sync(af, &As[wr * LDA2 + k], LDA2);
#pragma unroll
        for (int j = 0; j < 5; j++)
            wmma::load_matrix_sync(bf[j], &Bs[k * LDB2 + j * 16], LDB2);
#pragma unroll
        for (int j = 0; j < 5; j++) wmma::mma_sync(acc[j], af, bf[j], acc[j]);
    }
    __syncthreads();
#pragma unroll
    for (int j = 0; j < 5; j++)
        wmma::store_matrix_sync(&Cs[wr * LDB2 + j * 16], acc[j], LDB2,
                                wmma::mem_row_major);
    __syncthreads();

    // epilogue: 2 threads per row; half 0 -> y2h fp16 (cols 0..39), half 1 -> r2 + bias
    int row = tid >> 1, half = tid & 1;
    int m = node0 + row;
    if (m < n) {
        if (half == 0) {
            uint32_t* dst = (uint32_t*)&g_y2h[m * 40];
            const float* c = &Cs[row * LDB2];
#pragma unroll
            for (int j = 0; j < 40; j += 2) {
                __half2 h = __floats2half2_rn(c[j], c[j + 1]);
                dst[j >> 1] = *reinterpret_cast<uint32_t*>(&h);
            }
        } else {
            float4* dst = (float4*)&g_r2[m * 40];
            const float* c = &Cs[row * LDB2 + 40];
#pragma unroll
            for (int j = 0; j < 40; j += 4)
                dst[j >> 2] = make_float4(c[j] + bl[j], c[j + 1] + bl[j + 1],
                                          c[j + 2] + bl[j + 2], c[j + 3] + bl[j + 3]);
        }
    }
}

// ------- combine layer 1: hid = fp16(relu(gather_mean(y1) + r1)) --------
__global__ void combine1_kernel(int n) {
    int node = (blockIdx.x * blockDim.x + threadIdx.x) >> 5;
    int lane = threadIdx.x & 31;
    if (node >= n) return;
    int s = g_rowstart[node], e = g_rowstart[node + 1];
    float inv = 1.f / (float)max(e - s, 1);
    const __half2* y1 = (const __half2*)g_y1h;
    float a0 = 0.f, a1 = 0.f, b0 = 0.f, b1 = 0.f;
    float c0 = 0.f, c1 = 0.f, d0 = 0.f, d1 = 0.f;
    for (int base = s; base < e; base += 32) {
        int cnt = min(32, e - base);
        int idx = (lane < cnt) ? g_ebuf[base + lane] : 0;
        int j = 0;
        for (; j + 4 <= cnt; j += 4) {
            int n0 = __shfl_sync(0xffffffffu, idx, j);
            int n1 = __shfl_sync(0xffffffffu, idx, j + 1);
            int n2 = __shfl_sync(0xffffffffu, idx, j + 2);
            int n3 = __shfl_sync(0xffffffffu, idx, j + 3);
            float2 v0 = __half22float2(y1[n0 * 32 + lane]);
            float2 v1 = __half22float2(y1[n1 * 32 + lane]);
            float2 v2 = __half22float2(y1[n2 * 32 + lane]);
            float2 v3 = __half22float2(y1[n3 * 32 + lane]);
            a0 += v0.x; a1 += v0.y;
            b0 += v1.x; b1 += v1.y;
            c0 += v2.x; c1 += v2.y;
            d0 += v3.x; d1 += v3.y;
        }
        for (; j < cnt; j++) {
            int n0 = __shfl_sync(0xffffffffu, idx, j);
            float2 v0 = __half22float2(y1[n0 * 32 + lane]);
            a0 += v0.x; a1 += v0.y;
        }
    }
    a0 += b0 + c0 + d0;
    a1 += b1 + c1 + d1;
    float2 r = *(const float2*)&g_r1[node * 64 + lane * 2];
    float h0 = fmaxf(a0 * inv + r.x, 0.f);
    float h1 = fmaxf(a1 * inv + r.y, 0.f);
    *(__half2*)&g_hid[node * 64 + lane * 2] = __floats2half2_rn(h0, h1);
}

// ------- combine layer 2: out = log_softmax(gather_mean(y2) + r2) -------
__global__ void combine2_kernel(float* __restrict__ out, int n) {
    int node = (blockIdx.x * blockDim.x + threadIdx.x) >> 5;
    int lane = threadIdx.x & 31;
    if (node >= n) return;
    int s = g_rowstart[node], e = g_rowstart[node + 1];
    float inv = 1.f / (float)max(e - s, 1);
    const __half2* y2 = (const __half2*)g_y2h;
    bool act = lane < 20;
    float a0 = 0.f, a1 = 0.f, b0 = 0.f, b1 = 0.f;
    float c0 = 0.f, c1 = 0.f, d0 = 0.f, d1 = 0.f;
    for (int base = s; base < e; base += 32) {
        int cnt = min(32, e - base);
        int idx = (lane < cnt) ? g_ebuf[base + lane] : 0;
        int j = 0;
        for (; j + 4 <= cnt; j += 4) {
            int n0 = __shfl_sync(0xffffffffu, idx, j);
            int n1 = __shfl_sync(0xffffffffu, idx, j + 1);
            int n2 = __shfl_sync(0xffffffffu, idx, j + 2);
            int n3 = __shfl_sync(0xffffffffu, idx, j + 3);
            if (act) {
                float2 v0 = __half22float2(y2[n0 * 20 + lane]);
                float2 v1 = __half22float2(y2[n1 * 20 + lane]);
                float2 v2 = __half22float2(y2[n2 * 20 + lane]);
                float2 v3 = __half22float2(y2[n3 * 20 + lane]);
                a0 += v0.x; a1 += v0.y;
                b0 += v1.x; b1 += v1.y;
                c0 += v2.x; c1 += v2.y;
                d0 += v3.x; d1 += v3.y;
            }
        }
        for (; j < cnt; j++) {
            int n0 = __shfl_sync(0xffffffffu, idx, j);
            if (act) {
                float2 v0 = __half22float2(y2[n0 * 20 + lane]);
                a0 += v0.x; a1 += v0.y;
            }
        }
    }
    a0 += b0 + c0 + d0;
    a1 += b1 + c1 + d1;
    const float NEG_INF = __int_as_float(0xff800000);
    float v0 = NEG_INF, v1 = NEG_INF;
    if (act) {
        v0 = a0 * inv + g_r2[node * 40 + 2 * lane];
        v1 = a1 * inv + g_r2[node * 40 + 2 * lane + 1];
    }
    float m = fmaxf(v0, v1);
#pragma unroll
    for (int o = 16; o > 0; o >>= 1) m = fmaxf(m, __shfl_xor_sync(0xffffffffu, m, o));
    float sum = act ? (expf(v0 - m) + expf(v1 - m)) : 0.f;
#pragma unroll
    for (int o = 16; o > 0; o >>= 1) sum += __shfl_xor_sync(0xffffffffu, sum, o);
    float lse = logf(sum);
    if (act) {
        out[node * 40 + 2 * lane] = v0 - m - lse;
        out[node * 40 + 2 * lane + 1] = v1 - m - lse;
    }
}

// ---------------- launch ----------------
extern "C" void kernel_launch(void* const* d_in, const int* in_sizes, int n_in,
                              void* d_out, int out_size) {
    const float* x   = (const float*)d_in[0];
    const int*   ei  = (const int*)d_in[1];   // int64 inputs delivered as int32
    const float* Wl1 = (const float*)d_in[2];
    const float* bl1 = (const float*)d_in[3];
    const float* Wr1 = (const float*)d_in[4];
    const float* Wl2 = (const float*)d_in[5];
    const float* bl2 = (const float*)d_in[6];
    const float* Wr2 = (const float*)d_in[7];
    float* out = (float*)d_out;

    int n = in_sizes[0] / 128;
    int e = in_sizes[1] / 2;
    const int* src = ei;
    const int* dst = ei + e;

    const int SMEM1 = 128 * LDA1 * 2 * 2;          // 69632 B (A+B == C)
    const int SMEM2 = 128 * LDB2 * 4;              // 45056 B (C is the max)
    cudaFuncSetAttribute(gemm1_kernel, cudaFuncAttributeMaxDynamicSharedMemorySize, SMEM1);
    cudaFuncSetAttribute(gemm2_kernel, cudaFuncAttributeMaxDynamicSharedMemorySize, SMEM2);

    // Side stream: CSR build overlaps layer-1 GEMM
    cudaStream_t s2;
    cudaStreamCreateWithFlags(&s2, cudaStreamNonBlocking);
    cudaEvent_t evFork, evJoin;
    cudaEventCreateWithFlags(&evFork, cudaEventDisableTiming);
    cudaEventCreateWithFlags(&evJoin, cudaEventDisableTiming);

    cudaEventRecord(evFork, 0);
    cudaStreamWaitEvent(s2, evFork, 0);

    zero_kernel<<<(n + 255) / 256, 256, 0, s2>>>(n);
    count_deg_kernel<<<(e + 255) / 256, 256, 0, s2>>>(dst, e);
    int nb = (n + 1023) / 1024;
    scan1_kernel<<<nb, 1024, 0, s2>>>(n);
    scan2_kernel<<<1, 128, 0, s2>>>(nb);
    scan3_kernel<<<(n + 1 + 255) / 256, 256, 0, s2>>>(n, e);
    fill_csr_kernel<<<(e + 255) / 256, 256, 0, s2>>>(src, dst, e);
    cudaEventRecord(evJoin, s2);

    int nblk = (n + 127) / 128;
    gemm1_kernel<<<nblk, 256, SMEM1>>>(x, Wl1, Wr1, bl1, n);

    cudaStreamWaitEvent(0, evJoin, 0);
    combine1_kernel<<<(n * 32 + 255) / 256, 256>>>(n);
    gemm2_kernel<<<nblk, 256, SMEM2>>>(Wl2, Wr2, bl2, n);
    combine2_kernel<<<(n * 32 + 255) / 256, 256>>>(out, n);
}